// round 6
// baseline (speedup 1.0000x reference)
#include <cuda_runtime.h>
#include <cstdint>

#define N_ETA 7
#define FDIM 68
#define HW (512*1024)
#define CHUNK 480
#define SLOTS 512
#define NCHUNKS ((HW + CHUNK - 1) / CHUNK)   // 1093
#define WERT 5444        // expert stride in floats (68*80=5440 padded; mod 32 == 4)
#define WF 80            // per-f stride in floats (4 teams * 20)
#define FT 17            // f-tile rows (4 tiles cover 68)

__device__ unsigned char g_eta[HW];
__device__ int g_ctr;

// ---------------- threefry2x32, key (0,42), jax partitionable path ----------------
__device__ __forceinline__ void threefry2x32_k42(uint32_t& x0, uint32_t& x1) {
    const uint32_t K2 = 0x1BD11BDAu ^ 0u ^ 42u;
#define TFR(r) { x0 += x1; x1 = __funnelshift_l(x1, x1, (r)); x1 ^= x0; }
    x1 += 42u;
    TFR(13) TFR(15) TFR(26) TFR(6)
    x0 += 42u;  x1 += K2 + 1u;
    TFR(17) TFR(29) TFR(16) TFR(24)
    x0 += K2;   x1 += 0u + 2u;
    TFR(13) TFR(15) TFR(26) TFR(6)
    x1 += 42u + 3u;
    TFR(17) TFR(29) TFR(16) TFR(24)
    x0 += 42u;  x1 += K2 + 4u;
    TFR(13) TFR(15) TFR(26) TFR(6)
    x0 += K2;   x1 += 0u + 5u;
#undef TFR
}

__device__ __forceinline__ float gumbel_from_bits(uint32_t bits) {
    float f = __uint_as_float((bits >> 9) | 0x3F800000u) - 1.0f;
    const float tiny = 1.1754943508222875e-38f;
    float u = fmaxf(tiny, f + tiny);
    return -logf(-logf(u));
}

__global__ void eta_kernel(const float* __restrict__ T, const int* __restrict__ eta) {
    if (blockIdx.x == 0 && threadIdx.x == 0) g_ctr = 0;   // reset chunk counter each launch
    __shared__ float logT[N_ETA * N_ETA];
    if (threadIdx.x < N_ETA * N_ETA)
        logT[threadIdx.x] = logf(T[threadIdx.x] + 1e-9f);
    __syncthreads();

    int p = blockIdx.x * blockDim.x + threadIdx.x;
    if (p >= HW) return;
    int r = eta[p] * N_ETA;
    float best = -3.0e38f;
    int a = 0;
#pragma unroll
    for (int k = 0; k < N_ETA; k++) {
        uint32_t x0 = 0u;
        uint32_t x1 = (uint32_t)(p * 7 + k);
        threefry2x32_k42(x0, x1);
        uint32_t bits = x0 ^ x1;
        float v = logT[r + k] + gumbel_from_bits(bits);
        if (v > best) { best = v; a = k; }
    }
    g_eta[p] = (unsigned char)a;
}

// ---------------- packed f32x2 helpers ----------------
__device__ __forceinline__ unsigned long long pack_ff(float x, float y) {
    unsigned long long r;
    asm("mov.b64 %0, {%1, %2};" : "=l"(r) : "f"(x), "f"(y));
    return r;
}
__device__ __forceinline__ void unpack_ff(float& x, float& y, unsigned long long v) {
    asm("mov.b64 {%0, %1}, %2;" : "=f"(x), "=f"(y) : "l"(v));
}
__device__ __forceinline__ void fma2(unsigned long long& acc, unsigned long long w, unsigned long long v) {
    asm("fma.rn.f32x2 %0, %1, %2, %0;" : "+l"(acc) : "l"(w), "l"(v));
}
__device__ __forceinline__ void lds_v2u64(unsigned long long& a, unsigned long long& b, const float* p) {
    asm("ld.shared.v2.u64 {%0, %1}, [%2];"
        : "=l"(a), "=l"(b) : "l"(__cvta_generic_to_shared(p)));
}
__device__ __forceinline__ unsigned long long lds_u64(const float* p) {
    unsigned long long r;
    asm("ld.shared.u64 %0, [%1];" : "=l"(r) : "l"(__cvta_generic_to_shared(p)));
    return r;
}

// out[o,p] = sum_f W[e_p][o][f]*feat[f,p] + b[e_p][o]
// Per chunk of 480 pixels: sort by expert into groups of 4; lane processes 4
// same-expert pixels; 4 teams/warp split o as {18,18,16,16}; W reused 4x from regs.
__global__ __launch_bounds__(512, 1)
void compute_kernel(const float* __restrict__ feat, const float* __restrict__ W,
                    const float* __restrict__ b, float* __restrict__ out) {
    extern __shared__ float sh[];
    float* Ws     = sh;                          // 7 * WERT
    float* feat_s = Ws + N_ETA * WERT;           // FT * SLOTS (permuted)
    float* bs     = feat_s + FT * SLOTS;         // 7 * 68
    int*   o2s    = (int*)(bs + N_ETA * FDIM);   // CHUNK
    int*   s2o    = o2s + CHUNK;                 // SLOTS
    int*   meta   = s2o + SLOTS;                 // [0..7)=cnt [8..15)=start [16..23)=cur [24]=ngroups [25]=chunk

    const int tid = threadIdx.x;

    // zero W region (pads must be 0 so team-2/3 pair-8 reads are benign)
    for (int i = tid; i < N_ETA * WERT; i += 512) Ws[i] = 0.f;
    __syncthreads();
    // stage W into teamed layout: Ws[e*WERT + f*WF + t*20 + (o-obase)]
    for (int i = tid; i < N_ETA * FDIM * FDIM; i += 512) {
        int e = i / (FDIM * FDIM); int rem = i - e * FDIM * FDIM;
        int o = rem / FDIM; int f = rem - o * FDIM;
        int t  = (o < 18) ? 0 : (o < 36) ? 1 : (o < 52) ? 2 : 3;
        int ob = (t == 0) ? 0 : (t == 1) ? 18 : (t == 2) ? 36 : 52;
        Ws[e * WERT + f * WF + t * 20 + (o - ob)] = W[i];
    }
    for (int i = tid; i < N_ETA * FDIM; i += 512) bs[i] = b[i];

    const int lane = tid & 31, warp = tid >> 5;
    const int t = lane >> 3, gl = lane & 7;
    const int obase = (t == 0) ? 0 : (t == 1) ? 18 : (t == 2) ? 36 : 52;

    while (true) {
        __syncthreads();   // protects Ws staging (1st iter) and smem reuse across chunks
        if (tid == 0) meta[25] = atomicAdd(&g_ctr, 1);
        if (tid < 8) meta[tid] = 0;
        for (int i = tid; i < SLOTS; i += 512) s2o[i] = -1;
        __syncthreads();
        int c = meta[25];
        if (c >= NCHUNKS) break;
        int cb = c * CHUNK;
        int n = min(CHUNK, HW - cb);

        // histogram
        if (tid < n) atomicAdd(&meta[g_eta[cb + tid]], 1);
        __syncthreads();
        if (tid == 0) {
            int s = 0;
            for (int e = 0; e < N_ETA; e++) { meta[8 + e] = s; meta[16 + e] = s; s += (meta[e] + 3) & ~3; }
            meta[24] = s >> 2;   // ngroups (<=126)
        }
        __syncthreads();
        // scatter: sorted position per pixel
        if (tid < n) {
            int e = g_eta[cb + tid];
            int pos = atomicAdd(&meta[16 + e], 1);
            o2s[tid] = pos;
            s2o[pos] = tid;
        }
        __syncthreads();

        int ngroups = meta[24];
        int g = warp * 8 + gl;
        bool active = (g < ngroups);
        int myE = 0;
        int orig0 = -1, orig1 = -1, orig2 = -1, orig3 = -1;
        if (active) {
            orig0 = s2o[4 * g]; orig1 = s2o[4 * g + 1];
            orig2 = s2o[4 * g + 2]; orig3 = s2o[4 * g + 3];
            myE = g_eta[cb + orig0];   // group's first slot is always real
        }
        const float* wp = Ws + myE * WERT + t * 20;
        const float* bp = bs + myE * FDIM + obase;

        // init accumulators: acc[k*4 + px] holds (out[obase+2k], out[obase+2k+1]) for pixel px
        unsigned long long acc[36];
#pragma unroll
        for (int k = 0; k < 9; k++) {
            unsigned long long bb = 0ull;
            if (k < 8 || t < 2) bb = lds_u64(bp + 2 * k);
            acc[4 * k] = bb; acc[4 * k + 1] = bb; acc[4 * k + 2] = bb; acc[4 * k + 3] = bb;
        }

        // f-tiles
        for (int ft = 0; ft < 4; ft++) {
            int f0 = ft * FT;
            // stage permuted feat tile: coalesced LDG, scattered STS
            for (int idx = tid; idx < FT * CHUNK; idx += 512) {
                int fl = idx / CHUNK;
                int i  = idx - fl * CHUNK;
                if (i < n)
                    feat_s[fl * SLOTS + o2s[i]] = feat[(size_t)(f0 + fl) * HW + cb + i];
            }
            __syncthreads();
            if (active) {
                const float* wrow = wp + f0 * WF;
                const float* frow = feat_s + 4 * g;
#pragma unroll
                for (int fl = 0; fl < FT; fl++) {
                    float4 v4 = *(const float4*)(frow + fl * SLOTS);
                    unsigned long long vv0 = pack_ff(v4.x, v4.x);
                    unsigned long long vv1 = pack_ff(v4.y, v4.y);
                    unsigned long long vv2 = pack_ff(v4.z, v4.z);
                    unsigned long long vv3 = pack_ff(v4.w, v4.w);
                    unsigned long long w0, w1, w2, w3, w4, w5, w6, w7, w8;
                    lds_v2u64(w0, w1, wrow);
                    lds_v2u64(w2, w3, wrow + 4);
                    lds_v2u64(w4, w5, wrow + 8);
                    lds_v2u64(w6, w7, wrow + 12);
                    w8 = lds_u64(wrow + 16);          // zero pad for teams 2/3
                    fma2(acc[0],  w0, vv0); fma2(acc[1],  w0, vv1); fma2(acc[2],  w0, vv2); fma2(acc[3],  w0, vv3);
                    fma2(acc[4],  w1, vv0); fma2(acc[5],  w1, vv1); fma2(acc[6],  w1, vv2); fma2(acc[7],  w1, vv3);
                    fma2(acc[8],  w2, vv0); fma2(acc[9],  w2, vv1); fma2(acc[10], w2, vv2); fma2(acc[11], w2, vv3);
                    fma2(acc[12], w3, vv0); fma2(acc[13], w3, vv1); fma2(acc[14], w3, vv2); fma2(acc[15], w3, vv3);
                    fma2(acc[16], w4, vv0); fma2(acc[17], w4, vv1); fma2(acc[18], w4, vv2); fma2(acc[19], w4, vv3);
                    fma2(acc[20], w5, vv0); fma2(acc[21], w5, vv1); fma2(acc[22], w5, vv2); fma2(acc[23], w5, vv3);
                    fma2(acc[24], w6, vv0); fma2(acc[25], w6, vv1); fma2(acc[26], w6, vv2); fma2(acc[27], w6, vv3);
                    fma2(acc[28], w7, vv0); fma2(acc[29], w7, vv1); fma2(acc[30], w7, vv2); fma2(acc[31], w7, vv3);
                    fma2(acc[32], w8, vv0); fma2(acc[33], w8, vv1); fma2(acc[34], w8, vv2); fma2(acc[35], w8, vv3);
                    wrow += WF;
                }
            }
            __syncthreads();
        }

        // epilogue: scattered STG within the chunk window; L2 merges sectors
        if (active) {
#pragma unroll
            for (int k = 0; k < 9; k++) {
                if (k < 8 || t < 2) {
                    size_t ro0 = (size_t)(obase + 2 * k) * HW + cb;
                    size_t ro1 = ro0 + HW;
                    float x, y;
                    if (orig0 >= 0) { unpack_ff(x, y, acc[4 * k]);     out[ro0 + orig0] = x; out[ro1 + orig0] = y; }
                    if (orig1 >= 0) { unpack_ff(x, y, acc[4 * k + 1]); out[ro0 + orig1] = x; out[ro1 + orig1] = y; }
                    if (orig2 >= 0) { unpack_ff(x, y, acc[4 * k + 2]); out[ro0 + orig2] = x; out[ro1 + orig2] = y; }
                    if (orig3 >= 0) { unpack_ff(x, y, acc[4 * k + 3]); out[ro0 + orig3] = x; out[ro1 + orig3] = y; }
                }
            }
        }
    }
}

extern "C" void kernel_launch(void* const* d_in, const int* in_sizes, int n_in,
                              void* d_out, int out_size) {
    const float* x   = 0;   // 35,651,584
    const float* W   = 0;   // 32,368
    const float* b   = 0;   // 476
    const float* T   = 0;   // 49
    const int*   eta = 0;   // 524,288
    for (int i = 0; i < n_in; i++) {
        switch (in_sizes[i]) {
            case 35651584: x   = (const float*)d_in[i]; break;
            case 32368:    W   = (const float*)d_in[i]; break;
            case 476:      b   = (const float*)d_in[i]; break;
            case 49:       T   = (const float*)d_in[i]; break;
            case 524288:   eta = (const int*)d_in[i];   break;
        }
    }
    float* out = (float*)d_out;

    eta_kernel<<<HW / 256, 256>>>(T, eta);

    int smem = (N_ETA * WERT + FT * SLOTS + N_ETA * FDIM) * (int)sizeof(float)
             + (CHUNK + SLOTS + 26) * (int)sizeof(int);   // ~193 KB
    cudaFuncSetAttribute(compute_kernel, cudaFuncAttributeMaxDynamicSharedMemorySize, smem);
    int dev = 0, sms = 148;
    cudaGetDevice(&dev);
    cudaDeviceGetAttribute(&sms, cudaDevAttrMultiProcessorCount, dev);
    compute_kernel<<<sms, 512, smem>>>(x, W, b, out);
}